// round 8
// baseline (speedup 1.0000x reference)
#include <cuda_runtime.h>
#include <cstdint>

#define NJ 17
#define ROWSTRIDE 153          // 17*9 floats per timestep
#define NB 512                 // reduce blocks
#define SUB 32                 // staged timesteps per smem tile
#define NPART 1377             // 17*81 partial sums per block
#define NITER 450

__device__ float g_part[NB * NPART];
__device__ float g_M4[NPART];     // M4[n][ab][cd] flat
__device__ float g_sched[NITER];  // lr_t * sqrt(1-b2^t)/(1-b1^t)

// ---------------------------------------------------------------------------
// Kernel 1: coalesced one-pass reduction. Block handles a tchunk of timesteps,
// staging SUB full rows of A and B into smem via float4, then 153 threads
// (n,ab) accumulate acc[cd] += A[t,n,ab] * B[t,n,cd].
// ---------------------------------------------------------------------------
__global__ __launch_bounds__(256) void reduce2(
    const float* __restrict__ A, const float* __restrict__ B,
    int T, int tchunk)
{
    __shared__ float As[SUB * ROWSTRIDE];
    __shared__ float Bs[SUB * ROWSTRIDE];

    const int tid   = threadIdx.x;
    const int t0    = blockIdx.x * tchunk;
    const int i     = tid;               // (n,ab) for i < 153
    const int nbase = (i / 9) * 9;       // n*9

    float acc[9] = {0.f,0.f,0.f,0.f,0.f,0.f,0.f,0.f,0.f};

    for (int s = 0; s < tchunk; s += SUB) {
        const int tb   = t0 + s;
        const int rows = (T - tb < SUB) ? (T - tb) : SUB;
        if (rows <= 0) break;

        const float* Ag = A + (size_t)tb * ROWSTRIDE;
        const float* Bg = B + (size_t)tb * ROWSTRIDE;

        if (rows == SUB) {
            const float4* Ag4 = (const float4*)Ag;
            const float4* Bg4 = (const float4*)Bg;
            float4* As4 = (float4*)As;
            float4* Bs4 = (float4*)Bs;
#pragma unroll 3
            for (int j = tid; j < SUB * ROWSTRIDE / 4; j += 256) {
                As4[j] = Ag4[j];
                Bs4[j] = Bg4[j];
            }
        } else {
            for (int j = tid; j < rows * ROWSTRIDE; j += 256) {
                As[j] = Ag[j];
                Bs[j] = Bg[j];
            }
        }
        __syncthreads();

        if (i < NJ * 9) {
#pragma unroll 2
            for (int t = 0; t < rows; t++) {
                const float a  = As[t * ROWSTRIDE + i];
                const float* b = &Bs[t * ROWSTRIDE + nbase];
#pragma unroll
                for (int cd = 0; cd < 9; cd++)
                    acc[cd] = fmaf(a, b[cd], acc[cd]);
            }
        }
        __syncthreads();
    }

    if (i < NJ * 9) {
        float* p = g_part + (size_t)blockIdx.x * NPART + i * 9;
#pragma unroll
        for (int cd = 0; cd < 9; cd++) p[cd] = acc[cd];
    }
}

// ---------------------------------------------------------------------------
// Kernel 1b: deterministic double combine of partials + Adam schedule table.
// ---------------------------------------------------------------------------
__device__ __forceinline__ double dpowi(double base, int e) {
    double r = 1.0, b = base;
    while (e) { if (e & 1) r *= b; b *= b; e >>= 1; }
    return r;
}

__global__ void finalize_kernel(int nb)
{
    const int idx = blockIdx.x * blockDim.x + threadIdx.x;
    if (idx < NPART) {
        double s = 0.0;
        for (int b = 0; b < nb; b++)
            s += (double)g_part[b * NPART + idx];
        g_M4[idx] = (float)s;
    } else if (idx < NPART + NITER) {
        const int t = idx - NPART + 1;                  // 1..450
        const double lr = (t <= 150) ? 0.01 : ((t <= 300) ? 0.009 : 0.0081);
        const double b1p = dpowi(0.9, t);
        const double b2p = dpowi(0.999, t);
        g_sched[t - 1] = (float)(lr * sqrt(1.0 - b2p) / (1.0 - b1p));
    }
}

// ---------------------------------------------------------------------------
// Threefry-2x32-20 (exact JAX PRNG), key = jax.random.key(1) -> (0, 1)
// ---------------------------------------------------------------------------
__device__ __forceinline__ unsigned rotl32(unsigned x, int d) {
    return (x << d) | (x >> (32 - d));
}
__device__ __forceinline__ void tf_round4(unsigned& x0, unsigned& x1,
                                          int a, int b, int c, int d) {
    x0 += x1; x1 = rotl32(x1, a); x1 ^= x0;
    x0 += x1; x1 = rotl32(x1, b); x1 ^= x0;
    x0 += x1; x1 = rotl32(x1, c); x1 ^= x0;
    x0 += x1; x1 = rotl32(x1, d); x1 ^= x0;
}
__device__ __forceinline__ void threefry2x32_01(unsigned x0, unsigned x1,
                                                unsigned& o0, unsigned& o1) {
    const unsigned ks0 = 0u, ks1 = 1u, ks2 = 0x1BD11BDAu ^ 0u ^ 1u;
    x0 += ks0; x1 += ks1;
    tf_round4(x0, x1, 13, 15, 26, 6);  x0 += ks1; x1 += ks2 + 1u;
    tf_round4(x0, x1, 17, 29, 16, 24); x0 += ks2; x1 += ks0 + 2u;
    tf_round4(x0, x1, 13, 15, 26, 6);  x0 += ks0; x1 += ks1 + 3u;
    tf_round4(x0, x1, 17, 29, 16, 24); x0 += ks1; x1 += ks2 + 4u;
    tf_round4(x0, x1, 13, 15, 26, 6);  x0 += ks2; x1 += ks0 + 5u;
    o0 = x0; o1 = x1;
}

// ---------------------------------------------------------------------------
// Kernel 2: single-warp Adam solver. Lane n owns joint n; W (9x9, -2*lw
// folded) lives in registers; 450 iterations on-chip.
// ---------------------------------------------------------------------------
__global__ __launch_bounds__(32, 1) void solve_kernel(float* __restrict__ out)
{
    const int lane = threadIdx.x;
    const int n = (lane < NJ) ? lane : 0;
    const float* M = g_M4 + n * 81;

    // W[(p,q)][(j,k)] = -20 * ( M4[p,j,q,k] + M4[j,p,k,q] )
    float W[81];
#pragma unroll
    for (int p = 0; p < 3; p++)
#pragma unroll
    for (int q = 0; q < 3; q++)
#pragma unroll
    for (int j = 0; j < 3; j++)
#pragma unroll
    for (int k = 0; k < 3; k++) {
        float l1 = M[((p * 3 + j) * 3 + q) * 3 + k];
        float l2 = M[((j * 3 + p) * 3 + k) * 3 + q];
        W[(p * 3 + q) * 9 + (j * 3 + k)] = -20.0f * (l1 + l2);
    }

    // ang0 = uniform(key(1),(17,3)), partitionable threefry, XOR-fold
    float ang[3];
#pragma unroll
    for (int j = 0; j < 3; j++) {
        int i = n * 3 + j;
        unsigned o0, o1;
        threefry2x32_01(0u, (unsigned)i, o0, o1);
        unsigned bits = o0 ^ o1;
        ang[j] = __uint_as_float((bits >> 9) | 0x3F800000u) - 1.0f;
    }

    float m[3] = {0.f, 0.f, 0.f}, v[3] = {0.f, 0.f, 0.f};

    for (int it = 0; it < NITER; it++) {
        const float sc = g_sched[it];   // independent load, hidden by the body

        // Rodrigues
        float t2 = ang[0] * ang[0] + ang[1] * ang[1] + ang[2] * ang[2];
        float inv = rsqrtf(fmaxf(t2, 1e-24f));   // 1/theta
        float th = t2 * inv;
        float k0 = ang[0] * inv, k1 = ang[1] * inv, k2 = ang[2] * inv;
        float c = __cosf(th), s = __sinf(th);
        float omc = 1.0f - c;

        float C[9];
        {
            float ok0 = omc * k0, ok1 = omc * k1, ok2 = omc * k2;
            float sk0 = s * k0,   sk1 = s * k1,   sk2 = s * k2;
            C[0] = fmaf(ok0, k0,  c);
            C[1] = fmaf(ok0, k1, -sk2);
            C[2] = fmaf(ok0, k2,  sk1);
            C[3] = fmaf(ok1, k0,  sk2);
            C[4] = fmaf(ok1, k1,  c);
            C[5] = fmaf(ok1, k2, -sk0);
            C[6] = fmaf(ok2, k0, -sk1);
            C[7] = fmaf(ok2, k1,  sk0);
            C[8] = fmaf(ok2, k2,  c);
        }

        // Ambient gradient G = W * vec(C)
        float G[9];
#pragma unroll
        for (int p = 0; p < 9; p++) {
            float acc = W[p * 9] * C[0];
#pragma unroll
            for (int q = 1; q < 9; q++) acc = fmaf(W[p * 9 + q], C[q], acc);
            G[p] = acc;
        }

        // Rodrigues VJP: g_m = <G, dC/dr_m>
        float trG = G[0] + G[4] + G[8];
        float a0 = G[5] - G[7], a1 = G[6] - G[2], a2 = G[1] - G[3];
        float kda = k0 * a0 + k1 * a1 + k2 * a2;
        float u0 = G[0] * k0 + G[1] * k1 + G[2] * k2;   // G k
        float u1 = G[3] * k0 + G[4] * k1 + G[5] * k2;
        float u2 = G[6] * k0 + G[7] * k1 + G[8] * k2;
        float w0 = G[0] * k0 + G[3] * k1 + G[6] * k2;   // G^T k
        float w1 = G[1] * k0 + G[4] * k1 + G[7] * k2;
        float w2 = G[2] * k0 + G[5] * k1 + G[8] * k2;
        float kGk = k0 * u0 + k1 * u1 + k2 * u2;

        float coef = s * kGk - s * trG - c * kda;
        float so = s * inv, co = omc * inv;
        float tkGk = 2.0f * kGk;
        float g0 = k0 * coef + so * (kda * k0 - a0) + co * (u0 + w0 - tkGk * k0);
        float g1 = k1 * coef + so * (kda * k1 - a1) + co * (u1 + w1 - tkGk * k1);
        float g2 = k2 * coef + so * (kda * k2 - a2) + co * (u2 + w2 - tkGk * k2);
        float g[3] = {g0, g1, g2};

        // Adam, bias-correction + lr folded into sc; eps dropped
        // (|g| >> 1e-8 always; R4==R5 output proves insensitivity)
#pragma unroll
        for (int j = 0; j < 3; j++) {
            m[j] = fmaf(0.9f,   m[j], 0.1f   * g[j]);
            v[j] = fmaf(0.999f, v[j], 0.001f * (g[j] * g[j]));
            ang[j] -= (sc * m[j]) * rsqrtf(fmaxf(v[j], 1e-38f));
        }
    }

    if (lane < NJ) {
        out[n * 3 + 0] = ang[0];
        out[n * 3 + 1] = ang[1];
        out[n * 3 + 2] = ang[2];
    }
}

// ---------------------------------------------------------------------------
extern "C" void kernel_launch(void* const* d_in, const int* in_sizes, int n_in,
                              void* d_out, int out_size)
{
    const float* A = (const float*)d_in[0];   // orgGyros (T,17,3,3)
    const float* B = (const float*)d_in[1];   // trgGyros (T,17,3,3)
    const int T = in_sizes[0] / ROWSTRIDE;

    int tchunk = (T + NB - 1) / NB;
    tchunk = (tchunk + SUB - 1) / SUB * SUB;

    reduce2<<<NB, 256>>>(A, B, T, tchunk);
    finalize_kernel<<<(NPART + NITER + 255) / 256, 256>>>(NB);
    solve_kernel<<<1, 32>>>((float*)d_out);
}